// round 14
// baseline (speedup 1.0000x reference)
#include <cuda_runtime.h>
#include <cuda_fp16.h>

#define NX 20000
#define NL 48
#define NK 1024
#define NT 600
#define NSTRIPE 16
#define NQ 24                 // (table, ell-group-of-8): 4 tables x 6 groups
#define TPB (NQ * NSTRIPE)    // 384 threads
#define CH 38                 // contiguous tau-chunk length (16*38=608 >= 600)
#define DROLL 448             // deferred-coefficient path when row-span D <= DROLL

// Combined fp16 table: Ch[x][tbl*48 + ell], 192 halves (384B) per x-row.
__device__ __half g_Ch[NX * 192];

typedef unsigned long long u64;

// Bit-cast helpers (no SASS cost).
static __device__ __forceinline__ int h2_as_int(__half2 h) {
    return *reinterpret_cast<int*>(&h);
}
static __device__ __forceinline__ __half2 int_as_h2(int i) {
    return *reinterpret_cast<__half2*>(&i);
}

// Packed fp32x2 helpers (Blackwell f32x2 pipe; PTX-only encoding).
static __device__ __forceinline__ u64 pack2(float x, float y) {
    u64 r;
    asm("mov.b64 %0, {%1, %2};" : "=l"(r) : "f"(x), "f"(y));
    return r;
}
static __device__ __forceinline__ float2 unpack2(u64 v) {
    float2 f;
    asm("mov.b64 {%0, %1}, %2;" : "=f"(f.x), "=f"(f.y) : "l"(v));
    return f;
}
static __device__ __forceinline__ void ffma2(u64& acc, u64 a, u64 b) {
    asm("fma.rn.f32x2 %0, %1, %2, %0;" : "+l"(acc) : "l"(a), "l"(b));
}
// half2 -> packed float2 (two F2F; pack resolves to register placement).
static __device__ __forceinline__ u64 h2f2p(int h2bits) {
    float2 f = __half22float2(int_as_h2(h2bits));
    return pack2(f.x, f.y);
}

// ---------------------------------------------------------------------------
// Kernel 0: pack four [NX, NL] fp32 tables into one [NX, 192] fp16 table,
// AND zero the (poisoned / previously-accumulated) output.
// ---------------------------------------------------------------------------
__global__ __launch_bounds__(256) void kpack(
    const float* __restrict__ p0, const float* __restrict__ p1,
    const float* __restrict__ p2, const float* __restrict__ pe,
    float* __restrict__ out)
{
    if (blockIdx.x == 0 && threadIdx.x < 3 * NL)
        out[threadIdx.x] = 0.0f;

    int i = blockIdx.x * 256 + threadIdx.x;       // over NX*24
    int x   = i / 24;
    int sub = i % 24;
    int tbl = sub / 6;
    int eg  = sub % 6;

    const float* src = (tbl == 0 ? p0 : tbl == 1 ? p1 : tbl == 2 ? p2 : pe)
                       + x * NL + eg * 8;
    float4 va = *(const float4*)(src);
    float4 vb = *(const float4*)(src + 4);

    int4 pk;
    pk.x = h2_as_int(__floats2half2_rn(va.x, va.y));
    pk.y = h2_as_int(__floats2half2_rn(va.z, va.w));
    pk.z = h2_as_int(__floats2half2_rn(vb.x, vb.y));
    pk.w = h2_as_int(__floats2half2_rn(vb.z, vb.w));
    *(int4*)(g_Ch + x * 192 + tbl * 48 + eg * 8) = pk;
}

// ---------------------------------------------------------------------------
// Kernel 1: line-of-sight tau-integration + Cl accumulation. One block per k.
// Staging per tau: {row byte-offset, w as half2 bits}; per (table,tau):
// {c(1-w), c*w}. Accumulators are packed fp32x2 (FFMA2).
// Path A (D <= DROLL): deferred-coefficient rolling over contiguous chunks.
// Path B: strided gather, unroll-4.
// ---------------------------------------------------------------------------
__global__ __launch_bounds__(TPB) void klos(
    const float* __restrict__ k,  const float* __restrict__ tau,
    const float* __restrict__ tau0p, const float* __restrict__ bx,
    const float* __restrict__ S0, const float* __restrict__ S1,
    const float* __restrict__ S2, const float* __restrict__ SE,
    const float* __restrict__ Asp, const float* __restrict__ nsp,
    float* __restrict__ out)
{
    __shared__ float2 sCAB[4 * NT];  // {c(1-w), c*w} per (table, tau)
    __shared__ int2   siw[NT];       // {i0*384 (byte offset), half2(w) bits}
    __shared__ float  red[TPB * 8];
    __shared__ float  sscale;

    const int ik  = (NK - 1) - blockIdx.x;   // heavy (large-k) blocks first
    const int tid = threadIdx.x;

    const float kk   = k[ik];
    const float t0   = tau0p[0];
    const float xmin = bx[0];
    const float inv  = (float)(NX - 1) / (bx[NX - 1] - xmin);

    for (int t = tid; t < NT; t += TPB) {
        float tc = tau[t];
        float tp = (t + 1 < NT) ? tau[t + 1] : tc;
        float tm = (t > 0)      ? tau[t - 1] : tc;
        float wt = 0.5f * (tp - tm);
        float pos = (kk * (t0 - tc) - xmin) * inv;
        pos = fminf(fmaxf(pos, 0.0f), (float)(NX - 1));
        int i0 = (int)pos;
        if (i0 > NX - 2) i0 = NX - 2;
        float w  = pos - (float)i0;
        float wm = 1.0f - w;
        siw[t] = make_int2(i0 * 384, h2_as_int(__float2half2_rn(w)));
        float c0 = S0[ik * NT + t] * wt;
        float c1 = S1[ik * NT + t] * wt;
        float c2 = S2[ik * NT + t] * wt;
        float c3 = SE[ik * NT + t] * wt;
        sCAB[0 * NT + t] = make_float2(c0 * wm, c0 * w);
        sCAB[1 * NT + t] = make_float2(c1 * wm, c1 * w);
        sCAB[2 * NT + t] = make_float2(c2 * wm, c2 * w);
        sCAB[3 * NT + t] = make_float2(c3 * wm, c3 * w);
    }
    if (tid == 0) {
        // sqrt( (2/pi) * dk * k^2 * P_R(k) ), folded into T,E
        float kp = (ik + 1 < NK) ? k[ik + 1] : kk;
        float km = (ik > 0)      ? k[ik - 1] : kk;
        float dk = 0.5f * (kp - km);
        const float PI = 3.14159265358979323846f;
        float A_s = Asp[0], n_s = nsp[0];
        float pr = A_s * powf(kk * 20.0f, n_s - 1.0f)
                       * (2.0f * PI * PI / (kk * kk * kk));
        sscale = sqrtf((2.0f / PI) * dk * kk * kk * pr);
    }
    __syncthreads();

    // x decreases with t -> row offset monotone non-increasing.
    const int Db = siw[0].x - siw[NT - 1].x;   // byte descent across block

    const int q   = tid % NQ;
    const int st  = tid / NQ;
    const int tbl = q / 6;
    const float2* __restrict__ scab = sCAB + tbl * NT;
    const char* __restrict__ chbase = (const char*)g_Ch + q * 16;

    u64 a01 = 0ull, a23 = 0ull, a45 = 0ull, a67 = 0ull;

    if (Db <= DROLL * 384) {
        // ---- Path A: deferred-coefficient rolling sweep ----
        const int lo = st * CH;
        const int hi = (lo + CH < NT) ? lo + CH : NT;
        int cur = siw[lo].x;
        int4 Ar = *(const int4*)(chbase + cur);
        int4 Br = *(const int4*)(chbase + cur + 384);
        float gA = 0.f, gB = 0.f;

        for (int t = lo; t < hi; ++t) {
            int off = siw[t].x;
            if (off != cur) {
                // apply accumulated coefficients to the old row pair
                {
                    u64 gA2 = pack2(gA, gA);
                    u64 gB2 = pack2(gB, gB);
                    ffma2(a01, gA2, h2f2p(Ar.x)); ffma2(a01, gB2, h2f2p(Br.x));
                    ffma2(a23, gA2, h2f2p(Ar.y)); ffma2(a23, gB2, h2f2p(Br.y));
                    ffma2(a45, gA2, h2f2p(Ar.z)); ffma2(a45, gB2, h2f2p(Br.z));
                    ffma2(a67, gA2, h2f2p(Ar.w)); ffma2(a67, gB2, h2f2p(Br.w));
                }
                if (off == cur - 384) {
                    Br = Ar;
                    Ar = *(const int4*)(chbase + off);
                } else {
                    Ar = *(const int4*)(chbase + off);
                    Br = *(const int4*)(chbase + off + 384);
                }
                cur = off;
                gA = 0.f; gB = 0.f;
            }
            float2 cab = scab[t];
            gA += cab.x;
            gB += cab.y;
        }
        // final apply
        {
            u64 gA2 = pack2(gA, gA);
            u64 gB2 = pack2(gB, gB);
            ffma2(a01, gA2, h2f2p(Ar.x)); ffma2(a01, gB2, h2f2p(Br.x));
            ffma2(a23, gA2, h2f2p(Ar.y)); ffma2(a23, gB2, h2f2p(Br.y));
            ffma2(a45, gA2, h2f2p(Ar.z)); ffma2(a45, gB2, h2f2p(Br.z));
            ffma2(a67, gA2, h2f2p(Ar.w)); ffma2(a67, gB2, h2f2p(Br.w));
        }
    } else {
        // ---- Path B: strided gather, MLP via unroll ----
        #pragma unroll 4
        for (int t = st; t < NT; t += NSTRIPE) {
            int2  iw = siw[t];
            __half2 wh = int_as_h2(iw.y);

            const int4* pa = (const int4*)(chbase + iw.x);
            int4 Ar = pa[0];
            int4 Br = pa[24];      // next x-row: +384B

            __half2 A0 = int_as_h2(Ar.x), A1 = int_as_h2(Ar.y),
                    A2 = int_as_h2(Ar.z), A3 = int_as_h2(Ar.w);
            __half2 B0 = int_as_h2(Br.x), B1 = int_as_h2(Br.y),
                    B2 = int_as_h2(Br.z), B3 = int_as_h2(Br.w);

            int r0h = h2_as_int(__hfma2(__hsub2(B0, A0), wh, A0));
            int r1h = h2_as_int(__hfma2(__hsub2(B1, A1), wh, A1));
            int r2h = h2_as_int(__hfma2(__hsub2(B2, A2), wh, A2));
            int r3h = h2_as_int(__hfma2(__hsub2(B3, A3), wh, A3));

            float2 cab = scab[t];
            float c = cab.x + cab.y;
            u64 c2 = pack2(c, c);
            ffma2(a01, c2, h2f2p(r0h));
            ffma2(a23, c2, h2f2p(r1h));
            ffma2(a45, c2, h2f2p(r2h));
            ffma2(a67, c2, h2f2p(r3h));
        }
    }

    {
        float2 f01 = unpack2(a01), f23 = unpack2(a23),
               f45 = unpack2(a45), f67 = unpack2(a67);
        float* r = red + tid * 8;
        r[0]=f01.x; r[1]=f01.y; r[2]=f23.x; r[3]=f23.y;
        r[4]=f45.x; r[5]=f45.y; r[6]=f67.x; r[7]=f67.y;
    }
    __syncthreads();

    // 48 threads: thread ell sums its T (tables 0..2) and E (table 3) over
    // all stripes, scales, and accumulates Cl terms atomically.
    if (tid < NL) {
        int ell = tid;
        int g   = ell >> 3;
        int j   = ell & 7;
        float sT = 0.f, sE = 0.f;
        #pragma unroll
        for (int sp = 0; sp < NSTRIPE; sp++) {
            const float* base = red + (sp * NQ) * 8 + j;
            sT += base[(0 * 6 + g) * 8] + base[(1 * 6 + g) * 8] + base[(2 * 6 + g) * 8];
            sE += base[(3 * 6 + g) * 8];
        }
        float sc = sscale;
        float T = sT * sc, E = sE * sc;
        atomicAdd(&out[0 * NL + ell], T * T);
        atomicAdd(&out[1 * NL + ell], E * E);
        atomicAdd(&out[2 * NL + ell], T * E);
    }
}

// ---------------------------------------------------------------------------
extern "C" void kernel_launch(void* const* d_in, const int* in_sizes, int n_in,
                              void* d_out, int out_size)
{
    const float* k    = (const float*)d_in[0];
    const float* tau  = (const float*)d_in[1];
    const float* tau0 = (const float*)d_in[2];
    const float* S0   = (const float*)d_in[3];
    const float* S1   = (const float*)d_in[4];
    const float* S2   = (const float*)d_in[5];
    const float* SE   = (const float*)d_in[6];
    const float* bx   = (const float*)d_in[7];
    const float* p0   = (const float*)d_in[8];
    const float* p1   = (const float*)d_in[9];
    const float* p2   = (const float*)d_in[10];
    const float* pe   = (const float*)d_in[11];
    const float* A_s  = (const float*)d_in[12];
    const float* n_s  = (const float*)d_in[13];
    float* out = (float*)d_out;

    kpack<<<(NX * 24) / 256, 256>>>(p0, p1, p2, pe, out);
    klos<<<NK, TPB>>>(k, tau, tau0, bx, S0, S1, S2, SE, A_s, n_s, out);
}

// round 15
// speedup vs baseline: 1.1346x; 1.1346x over previous
#include <cuda_runtime.h>
#include <cuda_fp16.h>

#define NX 20000
#define NL 48
#define NK 1024
#define NT 600
#define NSTRIPE 16
#define NQ 24                 // (table, ell-group-of-8): 4 tables x 6 groups
#define TPB (NQ * NSTRIPE)    // 384 threads
#define CH 38                 // contiguous tau-chunk length (16*38=608 >= 600)
#define DROLL 448             // deferred-coefficient path when row-span D <= DROLL

// Combined fp16 table: Ch[x][tbl*48 + ell], 192 halves (384B) per x-row.
__device__ __half g_Ch[NX * 192];

// Bit-cast helpers (no SASS cost).
static __device__ __forceinline__ int h2_as_int(__half2 h) {
    return *reinterpret_cast<int*>(&h);
}
static __device__ __forceinline__ __half2 int_as_h2(int i) {
    return *reinterpret_cast<__half2*>(&i);
}

// ---------------------------------------------------------------------------
// Kernel 0: pack four [NX, NL] fp32 tables into one [NX, 192] fp16 table,
// AND zero the (poisoned / previously-accumulated) output.
// ---------------------------------------------------------------------------
__global__ __launch_bounds__(256) void kpack(
    const float* __restrict__ p0, const float* __restrict__ p1,
    const float* __restrict__ p2, const float* __restrict__ pe,
    float* __restrict__ out)
{
    if (blockIdx.x == 0 && threadIdx.x < 3 * NL)
        out[threadIdx.x] = 0.0f;

    int i = blockIdx.x * 256 + threadIdx.x;       // over NX*24
    int x   = i / 24;
    int sub = i % 24;
    int tbl = sub / 6;
    int eg  = sub % 6;

    const float* src = (tbl == 0 ? p0 : tbl == 1 ? p1 : tbl == 2 ? p2 : pe)
                       + x * NL + eg * 8;
    float4 va = *(const float4*)(src);
    float4 vb = *(const float4*)(src + 4);

    int4 pk;
    pk.x = h2_as_int(__floats2half2_rn(va.x, va.y));
    pk.y = h2_as_int(__floats2half2_rn(va.z, va.w));
    pk.z = h2_as_int(__floats2half2_rn(vb.x, vb.y));
    pk.w = h2_as_int(__floats2half2_rn(vb.z, vb.w));
    *(int4*)(g_Ch + x * 192 + tbl * 48 + eg * 8) = pk;
}

// ---------------------------------------------------------------------------
// Kernel 1: line-of-sight tau-integration + Cl accumulation. One block per k.
// Staging precomputes per (table, tau): {c(1-w), c*w} and per tau:
// {row byte-offset, w bits}. 5 blocks/SM pinned via launch_bounds.
// Path A (D <= DROLL): deferred-coefficient rolling over contiguous chunks.
// Path B: strided gather, unroll-2.
// ---------------------------------------------------------------------------
__global__ __launch_bounds__(TPB, 5) void klos(
    const float* __restrict__ k,  const float* __restrict__ tau,
    const float* __restrict__ tau0p, const float* __restrict__ bx,
    const float* __restrict__ S0, const float* __restrict__ S1,
    const float* __restrict__ S2, const float* __restrict__ SE,
    const float* __restrict__ Asp, const float* __restrict__ nsp,
    float* __restrict__ out)
{
    __shared__ float2 sCAB[4 * NT];  // {c(1-w), c*w} per (table, tau)
    __shared__ int2   siw[NT];       // {i0*384 (byte offset), bits(frac w)}
    __shared__ float  red[TPB * 8];
    __shared__ float  sscale;

    const int ik  = (NK - 1) - blockIdx.x;   // heavy (large-k) blocks first
    const int tid = threadIdx.x;

    const float kk   = k[ik];
    const float t0   = tau0p[0];
    const float xmin = bx[0];
    const float inv  = (float)(NX - 1) / (bx[NX - 1] - xmin);

    for (int t = tid; t < NT; t += TPB) {
        float tc = tau[t];
        float tp = (t + 1 < NT) ? tau[t + 1] : tc;
        float tm = (t > 0)      ? tau[t - 1] : tc;
        float wt = 0.5f * (tp - tm);
        float pos = (kk * (t0 - tc) - xmin) * inv;
        pos = fminf(fmaxf(pos, 0.0f), (float)(NX - 1));
        int i0 = (int)pos;
        if (i0 > NX - 2) i0 = NX - 2;
        float w  = pos - (float)i0;
        float wm = 1.0f - w;
        siw[t] = make_int2(i0 * 384, __float_as_int(w));
        float c0 = S0[ik * NT + t] * wt;
        float c1 = S1[ik * NT + t] * wt;
        float c2 = S2[ik * NT + t] * wt;
        float c3 = SE[ik * NT + t] * wt;
        sCAB[0 * NT + t] = make_float2(c0 * wm, c0 * w);
        sCAB[1 * NT + t] = make_float2(c1 * wm, c1 * w);
        sCAB[2 * NT + t] = make_float2(c2 * wm, c2 * w);
        sCAB[3 * NT + t] = make_float2(c3 * wm, c3 * w);
    }
    if (tid == 0) {
        // sqrt( (2/pi) * dk * k^2 * P_R(k) ), folded into T,E
        float kp = (ik + 1 < NK) ? k[ik + 1] : kk;
        float km = (ik > 0)      ? k[ik - 1] : kk;
        float dk = 0.5f * (kp - km);
        const float PI = 3.14159265358979323846f;
        float A_s = Asp[0], n_s = nsp[0];
        float pr = A_s * powf(kk * 20.0f, n_s - 1.0f)
                       * (2.0f * PI * PI / (kk * kk * kk));
        sscale = sqrtf((2.0f / PI) * dk * kk * kk * pr);
    }
    __syncthreads();

    // x decreases with t -> row offset monotone non-increasing.
    const int Db = siw[0].x - siw[NT - 1].x;   // byte descent across block

    const int q   = tid % NQ;
    const int st  = tid / NQ;
    const int tbl = q / 6;
    const float2* __restrict__ scab = sCAB + tbl * NT;
    const char* __restrict__ chbase = (const char*)g_Ch + q * 16;

    float a0=0.f,a1=0.f,a2=0.f,a3=0.f,a4=0.f,a5=0.f,a6=0.f,a7=0.f;

    if (Db <= DROLL * 384) {
        // ---- Path A: deferred-coefficient rolling sweep ----
        const int lo = st * CH;
        const int hi = (lo + CH < NT) ? lo + CH : NT;
        int cur = siw[lo].x;
        int4 Ar = *(const int4*)(chbase + cur);
        int4 Br = *(const int4*)(chbase + cur + 384);
        float gA = 0.f, gB = 0.f;

        for (int t = lo; t < hi; ++t) {
            int off = siw[t].x;
            if (off != cur) {
                // apply accumulated coefficients to the old row pair
                {
                    float2 fA0 = __half22float2(int_as_h2(Ar.x));
                    float2 fA1 = __half22float2(int_as_h2(Ar.y));
                    float2 fA2 = __half22float2(int_as_h2(Ar.z));
                    float2 fA3 = __half22float2(int_as_h2(Ar.w));
                    float2 fB0 = __half22float2(int_as_h2(Br.x));
                    float2 fB1 = __half22float2(int_as_h2(Br.y));
                    float2 fB2 = __half22float2(int_as_h2(Br.z));
                    float2 fB3 = __half22float2(int_as_h2(Br.w));
                    a0 = fmaf(gA, fA0.x, fmaf(gB, fB0.x, a0));
                    a1 = fmaf(gA, fA0.y, fmaf(gB, fB0.y, a1));
                    a2 = fmaf(gA, fA1.x, fmaf(gB, fB1.x, a2));
                    a3 = fmaf(gA, fA1.y, fmaf(gB, fB1.y, a3));
                    a4 = fmaf(gA, fA2.x, fmaf(gB, fB2.x, a4));
                    a5 = fmaf(gA, fA2.y, fmaf(gB, fB2.y, a5));
                    a6 = fmaf(gA, fA3.x, fmaf(gB, fB3.x, a6));
                    a7 = fmaf(gA, fA3.y, fmaf(gB, fB3.y, a7));
                }
                if (off == cur - 384) {
                    Br = Ar;
                    Ar = *(const int4*)(chbase + off);
                } else {
                    Ar = *(const int4*)(chbase + off);
                    Br = *(const int4*)(chbase + off + 384);
                }
                cur = off;
                gA = 0.f; gB = 0.f;
            }
            float2 cab = scab[t];
            gA += cab.x;
            gB += cab.y;
        }
        // final apply
        {
            float2 fA0 = __half22float2(int_as_h2(Ar.x));
            float2 fA1 = __half22float2(int_as_h2(Ar.y));
            float2 fA2 = __half22float2(int_as_h2(Ar.z));
            float2 fA3 = __half22float2(int_as_h2(Ar.w));
            float2 fB0 = __half22float2(int_as_h2(Br.x));
            float2 fB1 = __half22float2(int_as_h2(Br.y));
            float2 fB2 = __half22float2(int_as_h2(Br.z));
            float2 fB3 = __half22float2(int_as_h2(Br.w));
            a0 = fmaf(gA, fA0.x, fmaf(gB, fB0.x, a0));
            a1 = fmaf(gA, fA0.y, fmaf(gB, fB0.y, a1));
            a2 = fmaf(gA, fA1.x, fmaf(gB, fB1.x, a2));
            a3 = fmaf(gA, fA1.y, fmaf(gB, fB1.y, a3));
            a4 = fmaf(gA, fA2.x, fmaf(gB, fB2.x, a4));
            a5 = fmaf(gA, fA2.y, fmaf(gB, fB2.y, a5));
            a6 = fmaf(gA, fA3.x, fmaf(gB, fB3.x, a6));
            a7 = fmaf(gA, fA3.y, fmaf(gB, fB3.y, a7));
        }
    } else {
        // ---- Path B: strided gather, unroll-2 (keeps regs <= 34) ----
        #pragma unroll 2
        for (int t = st; t < NT; t += NSTRIPE) {
            int2  iw = siw[t];
            __half2 wh = __float2half2_rn(__int_as_float(iw.y));

            const int4* pa = (const int4*)(chbase + iw.x);
            int4 Ar = pa[0];
            int4 Br = pa[24];      // next x-row: +384B

            __half2 A0 = int_as_h2(Ar.x), A1 = int_as_h2(Ar.y),
                    A2 = int_as_h2(Ar.z), A3 = int_as_h2(Ar.w);
            __half2 B0 = int_as_h2(Br.x), B1 = int_as_h2(Br.y),
                    B2 = int_as_h2(Br.z), B3 = int_as_h2(Br.w);

            __half2 r0h = __hfma2(__hsub2(B0, A0), wh, A0);
            __half2 r1h = __hfma2(__hsub2(B1, A1), wh, A1);
            __half2 r2h = __hfma2(__hsub2(B2, A2), wh, A2);
            __half2 r3h = __hfma2(__hsub2(B3, A3), wh, A3);

            float2 f0 = __half22float2(r0h);
            float2 f1 = __half22float2(r1h);
            float2 f2 = __half22float2(r2h);
            float2 f3 = __half22float2(r3h);

            float2 cab = scab[t];
            float c = cab.x + cab.y;
            a0 = fmaf(c, f0.x, a0); a1 = fmaf(c, f0.y, a1);
            a2 = fmaf(c, f1.x, a2); a3 = fmaf(c, f1.y, a3);
            a4 = fmaf(c, f2.x, a4); a5 = fmaf(c, f2.y, a5);
            a6 = fmaf(c, f3.x, a6); a7 = fmaf(c, f3.y, a7);
        }
    }

    float* r = red + tid * 8;
    r[0]=a0; r[1]=a1; r[2]=a2; r[3]=a3; r[4]=a4; r[5]=a5; r[6]=a6; r[7]=a7;
    __syncthreads();

    // 48 threads: thread ell sums its T (tables 0..2) and E (table 3) over
    // all stripes, scales, and accumulates Cl terms atomically.
    if (tid < NL) {
        int ell = tid;
        int g   = ell >> 3;
        int j   = ell & 7;
        float sT = 0.f, sE = 0.f;
        #pragma unroll
        for (int sp = 0; sp < NSTRIPE; sp++) {
            const float* base = red + (sp * NQ) * 8 + j;
            sT += base[(0 * 6 + g) * 8] + base[(1 * 6 + g) * 8] + base[(2 * 6 + g) * 8];
            sE += base[(3 * 6 + g) * 8];
        }
        float sc = sscale;
        float T = sT * sc, E = sE * sc;
        atomicAdd(&out[0 * NL + ell], T * T);
        atomicAdd(&out[1 * NL + ell], E * E);
        atomicAdd(&out[2 * NL + ell], T * E);
    }
}

// ---------------------------------------------------------------------------
extern "C" void kernel_launch(void* const* d_in, const int* in_sizes, int n_in,
                              void* d_out, int out_size)
{
    const float* k    = (const float*)d_in[0];
    const float* tau  = (const float*)d_in[1];
    const float* tau0 = (const float*)d_in[2];
    const float* S0   = (const float*)d_in[3];
    const float* S1   = (const float*)d_in[4];
    const float* S2   = (const float*)d_in[5];
    const float* SE   = (const float*)d_in[6];
    const float* bx   = (const float*)d_in[7];
    const float* p0   = (const float*)d_in[8];
    const float* p1   = (const float*)d_in[9];
    const float* p2   = (const float*)d_in[10];
    const float* pe   = (const float*)d_in[11];
    const float* A_s  = (const float*)d_in[12];
    const float* n_s  = (const float*)d_in[13];
    float* out = (float*)d_out;

    kpack<<<(NX * 24) / 256, 256>>>(p0, p1, p2, pe, out);
    klos<<<NK, TPB>>>(k, tau, tau0, bx, S0, S1, S2, SE, A_s, n_s, out);
}